// round 8
// baseline (speedup 1.0000x reference)
#include <cuda_runtime.h>

// Problem constants (fixed by setup_inputs)
#define BATCH 2048
#define F 64
#define H 128
#define STEPS 101       // t + input_length = 100 + 1
#define LFRAMES 102     // total_length
#define DT 0.1f

#define GRID 148
#define THREADS 256     // 8 warps: w0-3 take 4 rows, w4-7 take 3 rows
#define NROWS 4096      // 2048 fwd + 2048 bwd row-jobs
#define ROWS_PER_CTA 28

// SMEM layout (float offsets). Pitch 129 => conflict-free for both
// row-contiguous (forward) and row-strided (transposed/backward) access.
#define P1 129
#define OFF_W1 0
#define OFF_W2 (OFF_W1 + 64 * P1)      // 8256
#define OFF_W3 (OFF_W2 + 128 * P1)     // 24768
#define OFF_B1 (OFF_W3 + 128 * P1)     // 41280
#define OFF_B2 (OFF_B1 + 128)
#define OFF_B3 (OFF_B2 + 128)
#define OFF_V  (OFF_B3 + 128)
#define OFF_BUF (OFF_V + 128)          // 41792
#define WARP_BUF 1280                  // per-warp: bufY 256 + bufA 512 + bufB 512
#define SMEM_FLOATS (OFF_BUF + 8 * WARP_BUF)  // 52032 floats = 208128 B

// Backward-trajectory scratch (device global: allocation-free)
__device__ __align__(16) float g_back[(size_t)BATCH * LFRAMES * F];

__device__ __forceinline__ float mytanh(float x) { return tanhf(x); }

// Forward matvec: acc[q][r] += sum_i buf[r][i] * W[i][lane+32q]
template <int IN, int NR>
__device__ __forceinline__ void matvec_fwd(const float* __restrict__ Wsm,
                                           const float* __restrict__ buf,
                                           float acc[4][NR], int lane) {
#pragma unroll 1
  for (int i = 0; i < IN; i += 4) {
    float4 a[NR];
#pragma unroll
    for (int r = 0; r < NR; r++) a[r] = *(const float4*)(buf + r * IN + i);
    const float* wrow = Wsm + i * P1 + lane;
#pragma unroll
    for (int ii = 0; ii < 4; ii++) {
#pragma unroll
      for (int q = 0; q < 4; q++) {
        float w = wrow[ii * P1 + 32 * q];
#pragma unroll
        for (int r = 0; r < NR; r++)
          acc[q][r] += w * ((const float*)&a[r])[ii];
      }
    }
  }
}

// Backward (transposed) matvec: acc[q][r] += sum_j W[lane+32q][j] * buf[r][j]
template <int QN, int NR>
__device__ __forceinline__ void matvec_bwd(const float* __restrict__ Wsm,
                                           const float* __restrict__ buf,
                                           float acc[QN][NR], int lane) {
  const float* wr[QN];
#pragma unroll
  for (int q = 0; q < QN; q++) wr[q] = Wsm + (lane + 32 * q) * P1;
#pragma unroll 1
  for (int j = 0; j < 128; j += 4) {
    float4 d[NR];
#pragma unroll
    for (int r = 0; r < NR; r++) d[r] = *(const float4*)(buf + r * 128 + j);
#pragma unroll
    for (int jj = 0; jj < 4; jj++) {
#pragma unroll
      for (int q = 0; q < QN; q++) {
        float w = wr[q][j + jj];
#pragma unroll
        for (int r = 0; r < NR; r++)
          acc[q][r] += w * ((const float*)&d[r])[jj];
      }
    }
  }
}

template <int NR>
__device__ __forceinline__ void run_job(float* __restrict__ sm, int warp,
                                        int lane, int row0,
                                        const float* __restrict__ x,
                                        float* __restrict__ out) {
  float* bufY = sm + OFF_BUF + warp * WARP_BUF;  // [NR][64]
  float* bufA = bufY + 256;                      // [NR][128]
  float* bufB = bufY + 768;                      // [NR][128]

  float y0[NR], y1[NR];
  float* obase[NR];
  float sgn[NR];
  bool bwdr[NR];
#pragma unroll
  for (int r = 0; r < NR; r++) {
    int row = row0 + r;
    if (row > NROWS - 1) row = NROWS - 1;   // clamp: duplicates are identical
    const bool bwd = (row >= NROWS / 2);
    const int b = row & (BATCH - 1);
    bwdr[r] = bwd;
    sgn[r] = bwd ? -1.0f : 1.0f;
    const float* xp = x + ((size_t)b * 2 + (bwd ? 1 : 0)) * F;
    y0[r] = xp[lane];
    y1[r] = sgn[r] * xp[lane + 32];  // vflip on backward init
    obase[r] = (bwd ? g_back : out) + (size_t)b * LFRAMES * F;
  }
  const float inv101 = 1.0f / 101.0f;

  // frame 0 (weight = 1); backward frame k lands at index LFRAMES-1-k
#pragma unroll
  for (int r = 0; r < NR; r++) {
    float* p = obase[r] + (bwdr[r] ? (LFRAMES - 1) : 0) * F;
    p[lane] = y0[r];
    p[lane + 32] = sgn[r] * y1[r];
  }

#pragma unroll 1
  for (int k = 1; k <= STEPS; k++) {
    __syncwarp();
#pragma unroll
    for (int r = 0; r < NR; r++) {
      bufY[r * 64 + lane] = y0[r];
      bufY[r * 64 + 32 + lane] = y1[r];
    }
    __syncwarp();

    float h1v[4][NR], h2v[4][NR], acc[4][NR];

    // ---- stage 1: h1 = tanh(y@W1 + b1) ----
#pragma unroll
    for (int q = 0; q < 4; q++) {
      float b = sm[OFF_B1 + lane + 32 * q];
#pragma unroll
      for (int r = 0; r < NR; r++) acc[q][r] = b;
    }
    matvec_fwd<64, NR>(sm + OFF_W1, bufY, acc, lane);
#pragma unroll
    for (int q = 0; q < 4; q++)
#pragma unroll
      for (int r = 0; r < NR; r++) h1v[q][r] = mytanh(acc[q][r]);
    __syncwarp();
#pragma unroll
    for (int q = 0; q < 4; q++)
#pragma unroll
      for (int r = 0; r < NR; r++) bufA[r * 128 + lane + 32 * q] = h1v[q][r];
    __syncwarp();

    // ---- stage 2: h2 = tanh(h1@W2 + b2) ----
#pragma unroll
    for (int q = 0; q < 4; q++) {
      float b = sm[OFF_B2 + lane + 32 * q];
#pragma unroll
      for (int r = 0; r < NR; r++) acc[q][r] = b;
    }
    matvec_fwd<128, NR>(sm + OFF_W2, bufA, acc, lane);
#pragma unroll
    for (int q = 0; q < 4; q++)
#pragma unroll
      for (int r = 0; r < NR; r++) h2v[q][r] = mytanh(acc[q][r]);
    __syncwarp();
#pragma unroll
    for (int q = 0; q < 4; q++)
#pragma unroll
      for (int r = 0; r < NR; r++) bufB[r * 128 + lane + 32 * q] = h2v[q][r];
    __syncwarp();

    // ---- stage 3: h3 = tanh(h2@W3 + b3); d3 = v * (1 - h3^2) ----
#pragma unroll
    for (int q = 0; q < 4; q++) {
      float b = sm[OFF_B3 + lane + 32 * q];
#pragma unroll
      for (int r = 0; r < NR; r++) acc[q][r] = b;
    }
    matvec_fwd<128, NR>(sm + OFF_W3, bufB, acc, lane);
    __syncwarp();
#pragma unroll
    for (int q = 0; q < 4; q++) {
      float vq = sm[OFF_V + lane + 32 * q];
#pragma unroll
      for (int r = 0; r < NR; r++) {
        float t = mytanh(acc[q][r]);
        bufA[r * 128 + lane + 32 * q] = vq * (1.0f - t * t);  // d3
      }
    }
    __syncwarp();

    // ---- backward 1: d2 = (W3 @ d3) * (1 - h2^2) ----
#pragma unroll
    for (int q = 0; q < 4; q++)
#pragma unroll
      for (int r = 0; r < NR; r++) acc[q][r] = 0.0f;
    matvec_bwd<4, NR>(sm + OFF_W3, bufA, acc, lane);
    __syncwarp();
#pragma unroll
    for (int q = 0; q < 4; q++)
#pragma unroll
      for (int r = 0; r < NR; r++)
        bufB[r * 128 + lane + 32 * q] =
            acc[q][r] * (1.0f - h2v[q][r] * h2v[q][r]);
    __syncwarp();

    // ---- backward 2: d1 = (W2 @ d2) * (1 - h1^2) ----
#pragma unroll
    for (int q = 0; q < 4; q++)
#pragma unroll
      for (int r = 0; r < NR; r++) acc[q][r] = 0.0f;
    matvec_bwd<4, NR>(sm + OFF_W2, bufB, acc, lane);
    __syncwarp();
#pragma unroll
    for (int q = 0; q < 4; q++)
#pragma unroll
      for (int r = 0; r < NR; r++)
        bufA[r * 128 + lane + 32 * q] =
            acc[q][r] * (1.0f - h1v[q][r] * h1v[q][r]);
    __syncwarp();

    // ---- backward 3: g = W1 @ d1 (64 outputs: q = 0,1) ----
    float gacc[2][NR];
#pragma unroll
    for (int q = 0; q < 2; q++)
#pragma unroll
      for (int r = 0; r < NR; r++) gacc[q][r] = 0.0f;
    matvec_bwd<2, NR>(sm + OFF_W1, bufA, gacc, lane);

    // ---- symplectic-style update + emit weighted frame ----
    const float s = (float)(101 - k) * inv101;  // w0(k) fwd == w1(L-1-k) bwd
#pragma unroll
    for (int r = 0; r < NR; r++) {
      y0[r] += DT * gacc[1][r];  // f = lane    (< 32): +g[f+32]
      y1[r] -= DT * gacc[0][r];  // f = lane+32 (>=32): -g[f-32]
      float* p = obase[r] + (bwdr[r] ? (LFRAMES - 1 - k) : k) * F;
      p[lane] = y0[r] * s;
      p[lane + 32] = sgn[r] * y1[r] * s;
    }
  }
}

__global__ void __launch_bounds__(THREADS, 1)
ham_kernel(const float* __restrict__ x,
           const float* __restrict__ W1, const float* __restrict__ b1,
           const float* __restrict__ W2, const float* __restrict__ b2,
           const float* __restrict__ W3, const float* __restrict__ b3,
           const float* __restrict__ W4, const float* __restrict__ W5,
           float* __restrict__ out) {
  extern __shared__ float sm[];
  const int tid = threadIdx.x;

  // ---- Stage weights into SMEM (pitch P1) ----
  for (int idx = tid; idx < 64 * H; idx += THREADS)
    sm[OFF_W1 + (idx >> 7) * P1 + (idx & 127)] = W1[idx];
  for (int idx = tid; idx < H * H; idx += THREADS)
    sm[OFF_W2 + (idx >> 7) * P1 + (idx & 127)] = W2[idx];
  for (int idx = tid; idx < H * H; idx += THREADS)
    sm[OFF_W3 + (idx >> 7) * P1 + (idx & 127)] = W3[idx];
  for (int idx = tid; idx < H; idx += THREADS) {
    sm[OFF_B1 + idx] = b1[idx];
    sm[OFF_B2 + idx] = b2[idx];
    sm[OFF_B3 + idx] = b3[idx];
  }
  if (tid < H) {  // v = W4 @ W5[:,0] (constant cotangent of h3)
    float acc = 0.0f;
    for (int k = 0; k < H; k++) acc += W4[tid * H + k] * W5[k];
    sm[OFF_V + tid] = acc;
  }
  __syncthreads();

  const int warp = tid >> 5;
  const int lane = tid & 31;

  // Warps 0-3 (one per SMSP) take 4 rows; warps 4-7 take 3 rows.
  // => every SMSP carries exactly 7 rows (ideal 6.92).
  const int cta_base = blockIdx.x * ROWS_PER_CTA;
  if (warp < 4) {
    const int row0 = cta_base + warp * 4;
    run_job<4>(sm, warp, lane, row0, x, out);
  } else {
    const int row0 = cta_base + 16 + (warp - 4) * 3;
    run_job<3>(sm, warp, lane, row0, x, out);
  }
}

__global__ void combine_kernel(float4* __restrict__ out, int n4) {
  const float4* __restrict__ gb = (const float4*)g_back;
  int i = blockIdx.x * blockDim.x + threadIdx.x;
  const int stride = gridDim.x * blockDim.x;
  for (; i < n4; i += stride) {
    float4 o = out[i];
    float4 g = gb[i];
    o.x += g.x; o.y += g.y; o.z += g.z; o.w += g.w;
    out[i] = o;
  }
}

extern "C" void kernel_launch(void* const* d_in, const int* in_sizes, int n_in,
                              void* d_out, int out_size) {
  (void)in_sizes; (void)n_in; (void)out_size;
  // metadata order: t, x, W1, b1, W2, b2, W3, b3, W4, b4, W5, b5
  const float* x  = (const float*)d_in[1];
  const float* W1 = (const float*)d_in[2];
  const float* b1 = (const float*)d_in[3];
  const float* W2 = (const float*)d_in[4];
  const float* b2 = (const float*)d_in[5];
  const float* W3 = (const float*)d_in[6];
  const float* b3 = (const float*)d_in[7];
  const float* W4 = (const float*)d_in[8];
  const float* W5 = (const float*)d_in[10];
  float* out = (float*)d_out;

  cudaFuncSetAttribute(ham_kernel, cudaFuncAttributeMaxDynamicSharedMemorySize,
                       SMEM_FLOATS * (int)sizeof(float));

  ham_kernel<<<GRID, THREADS, SMEM_FLOATS * (int)sizeof(float)>>>(
      x, W1, b1, W2, b2, W3, b3, W4, W5, out);

  const int n4 = (BATCH * LFRAMES * F) / 4;
  combine_kernel<<<1024, 256>>>((float4*)out, n4);
}